// round 14
// baseline (speedup 1.0000x reference)
#include <cuda_runtime.h>
#include <cuda_bf16.h>
#include <math.h>
#include <cstdint>

#define Bv 2
#define Cv 4
#define Fv 512
#define Hv 8
#define Wv 1024
#define DHv 64
#define BCv (Bv*Cv)                 // 8
#define FWv (Fv*Wv)                 // 524288
#define BCFWv ((size_t)BCv*FWv)     // 4194304

typedef __nv_bfloat16 bf16;

// ---------------- scratch (device globals; no allocations allowed) ----------
__device__ __align__(256) float g_lin[3*BCFWv];        // post mc_linear q/k/v (fp32)
__device__ __align__(256) bf16 g_whi[4*(size_t)Cv*Fv*Fv];
__device__ __align__(256) bf16 g_wlo[4*(size_t)Cv*Fv*Fv];
__device__ __align__(256) bf16 g_xt_hi[BCFWv];         // x^T [bc][w][f]
__device__ __align__(256) bf16 g_xt_lo[BCFWv];
__device__ __align__(256) bf16 g_qb[BCFWv];            // q [bc][f][w]  (f = h*64+d)
__device__ __align__(256) bf16 g_kb[BCFWv];            // k [bc][f][w]
__device__ __align__(256) bf16 g_vb_hi[BCFWv];         // v [bc][f][w]
__device__ __align__(256) bf16 g_vb_lo[BCFWv];
__device__ __align__(256) bf16 g_at_hi[BCFWv];         // attn out [bc][w][f]
__device__ __align__(256) bf16 g_at_lo[BCFWv];

// ============================================================================
// mma.sync / ldmatrix / cp.async helpers
// ============================================================================
__device__ __forceinline__ uint32_t smem_u32(const void* p) {
    uint32_t a;
    asm("{ .reg .u64 t; cvta.to.shared.u64 t, %1; cvt.u32.u64 %0, t; }" : "=r"(a) : "l"(p));
    return a;
}
__device__ __forceinline__ void ldsm4(uint32_t* r, uint32_t addr) {
    asm volatile("ldmatrix.sync.aligned.m8n8.x4.shared.b16 {%0,%1,%2,%3}, [%4];"
        : "=r"(r[0]), "=r"(r[1]), "=r"(r[2]), "=r"(r[3]) : "r"(addr));
}
__device__ __forceinline__ void ldsm4t(uint32_t* r, uint32_t addr) {
    asm volatile("ldmatrix.sync.aligned.m8n8.x4.trans.shared.b16 {%0,%1,%2,%3}, [%4];"
        : "=r"(r[0]), "=r"(r[1]), "=r"(r[2]), "=r"(r[3]) : "r"(addr));
}
__device__ __forceinline__ void mma16816(float* c, const uint32_t* a, const uint32_t* b) {
    asm volatile("mma.sync.aligned.m16n8k16.row.col.f32.bf16.bf16.f32 "
        "{%0,%1,%2,%3}, {%4,%5,%6,%7}, {%8,%9}, {%0,%1,%2,%3};"
        : "+f"(c[0]), "+f"(c[1]), "+f"(c[2]), "+f"(c[3])
        : "r"(a[0]), "r"(a[1]), "r"(a[2]), "r"(a[3]), "r"(b[0]), "r"(b[1]));
}
__device__ __forceinline__ void cp16(uint32_t saddr, const void* g) {
    asm volatile("cp.async.cg.shared.global [%0], [%1], 16;" :: "r"(saddr), "l"(g));
}
#define CP_COMMIT() asm volatile("cp.async.commit_group;")
#define CP_WAIT(n)  asm volatile("cp.async.wait_group %0;" :: "n"(n))

__device__ __forceinline__ void split_bf16(float v, bf16& h, bf16& l) {
    h = __float2bfloat16(v);
    l = __float2bfloat16(v - __bfloat162float(h));
}
__device__ __forceinline__ void pack2(float a, float b, uint32_t& hi, uint32_t& lo) {
    bf16 ha, la, hb, lb;
    split_bf16(a, ha, la);
    split_bf16(b, hb, lb);
    __nv_bfloat162 th{ha, hb}, tl{la, lb};
    hi = *(uint32_t*)&th;
    lo = *(uint32_t*)&tl;
}

// ============================================================================
// Conversion kernels
// ============================================================================
__global__ __launch_bounds__(256)
void cvt_weights(const float* __restrict__ w0, const float* __restrict__ w1,
                 const float* __restrict__ w2, const float* __restrict__ w3)
{
    size_t t = (size_t)blockIdx.x * 256 + threadIdx.x;   // 4 * 1M
    int m = (int)(t >> 20);
    const float* src = (m == 0) ? w0 : (m == 1) ? w1 : (m == 2) ? w2 : w3;
    float v = src[t & 1048575];
    bf16 h, l;
    split_bf16(v, h, l);
    g_whi[t] = h;
    g_wlo[t] = l;
}

__global__ __launch_bounds__(256)
void transpose_x(const float* __restrict__ x)
{
    __shared__ float tile[32][33];
    const int bc = blockIdx.z;
    const int w0 = blockIdx.x * 32, f0 = blockIdx.y * 32;
    const int tx = threadIdx.x & 31, ty = threadIdx.x >> 5;   // 32 x 8
    const float* src = x + (size_t)bc * FWv;
#pragma unroll
    for (int r = 0; r < 32; r += 8)
        tile[ty + r][tx] = src[(size_t)(f0 + ty + r) * Wv + w0 + tx];
    __syncthreads();
    bf16* hi = g_xt_hi + (size_t)bc * FWv;
    bf16* lo = g_xt_lo + (size_t)bc * FWv;
#pragma unroll
    for (int r = 0; r < 32; r += 8) {
        float v = tile[tx][ty + r];
        size_t idx = (size_t)(w0 + ty + r) * Fv + f0 + tx;
        bf16 h, l;
        split_bf16(v, h, l);
        hi[idx] = h;
        lo[idx] = l;
    }
}

// ============================================================================
// Per-channel GEMM via mma.sync, split hi/lo (3 products), cp.async
// double-buffered. 512 threads, 4x4 warp grid, warp tile 32x32.
// Dynamic smem: 2 bufs x 4 tiles(Ah,Al,Bh,Bl) x [128][40] bf16 = 81920 B.
// grid z = nsets*8: s = z>>3 selects weight set, bc = z&7.
// ============================================================================
#define GT_TILE 5120                           // 128*40 elems
#define GEMM_SMEM (2 * 4 * GT_TILE * 2)        // 81920 B

__global__ __launch_bounds__(512)
void mc_gemm_mma(const bf16* __restrict__ Whi, const bf16* __restrict__ Wlo,
                 const bf16* __restrict__ Xhi, const bf16* __restrict__ Xlo,
                 float* __restrict__ Y)
{
    extern __shared__ bf16 smg[];
    // tile(b,t): smg + (b*4+t)*GT_TILE ; layout [row][k] with 40-pad

    const int tid = threadIdx.x, lane = tid & 31, wid = tid >> 5;
    const int wm = wid >> 2, wn = wid & 3;          // 4 x 4 warps
    const int s = blockIdx.z >> 3, bc = blockIdx.z & 7, c = bc & 3;
    const int m0 = blockIdx.y * 128, n0 = blockIdx.x * 128;

    const bf16* Ah = Whi + ((size_t)s * Cv + c) * Fv * Fv;
    const bf16* Al = Wlo + ((size_t)s * Cv + c) * Fv * Fv;
    const bf16* Bh = Xhi + (size_t)bc * FWv;
    const bf16* Bl = Xlo + (size_t)bc * FWv;
    float* Cy = Y + ((size_t)s * BCv + bc) * FWv;

    const int g_row = tid >> 2;            // 0..127
    const int g_kc  = (tid & 3) * 8;

    const uint32_t smg_base = smem_u32(smg);
    auto load_stage = [&](int st) {
        const int b = st & 1;
        const int k0 = st * 32;
        const uint32_t soff = (b * 4 * GT_TILE + g_row * 40 + g_kc) * 2;
        cp16(smg_base + soff,                 Ah + (size_t)(m0 + g_row) * Fv + k0 + g_kc);
        cp16(smg_base + soff + GT_TILE * 2,   Al + (size_t)(m0 + g_row) * Fv + k0 + g_kc);
        cp16(smg_base + soff + GT_TILE * 4,   Bh + (size_t)(n0 + g_row) * Fv + k0 + g_kc);
        cp16(smg_base + soff + GT_TILE * 6,   Bl + (size_t)(n0 + g_row) * Fv + k0 + g_kc);
        CP_COMMIT();
    };

    float acc[2][4][4];
#pragma unroll
    for (int i = 0; i < 2; i++)
#pragma unroll
        for (int j = 0; j < 4; j++)
#pragma unroll
            for (int q = 0; q < 4; q++) acc[i][j][q] = 0.f;

    load_stage(0);
    const int NIT = Fv / 32;               // 16
    for (int it = 0; it < NIT; it++) {
        const int b = it & 1;
        if (it + 1 < NIT) { load_stage(it + 1); CP_WAIT(1); }
        else              { CP_WAIT(0); }
        __syncthreads();

        const bf16* Ahs = smg + (b * 4 + 0) * GT_TILE;
        const bf16* Als = smg + (b * 4 + 1) * GT_TILE;
        const bf16* Bhs = smg + (b * 4 + 2) * GT_TILE;
        const bf16* Bls = smg + (b * 4 + 3) * GT_TILE;

#pragma unroll
        for (int ks = 0; ks < 2; ks++) {
            uint32_t afh[2][4], afl[2][4], bfh[2][4], bfl[2][4];
            const int acol = ks * 16 + (lane >> 4) * 8;
            const int arow_l = lane & 15;
#pragma unroll
            for (int mf = 0; mf < 2; mf++) {
                const int r = wm * 32 + mf * 16 + arow_l;
                ldsm4(afh[mf], smem_u32(Ahs + r * 40 + acol));
                ldsm4(afl[mf], smem_u32(Als + r * 40 + acol));
            }
            const int brow_l = (lane & 7) + ((lane >> 4) & 1) * 8;
            const int bcol = ks * 16 + ((lane >> 3) & 1) * 8;
#pragma unroll
            for (int nh = 0; nh < 2; nh++) {
                const int r = wn * 32 + nh * 16 + brow_l;
                ldsm4(bfh[nh], smem_u32(Bhs + r * 40 + bcol));
                ldsm4(bfl[nh], smem_u32(Bls + r * 40 + bcol));
            }
#pragma unroll
            for (int mf = 0; mf < 2; mf++)
#pragma unroll
                for (int nf = 0; nf < 4; nf++) {
                    const uint32_t* bh = &bfh[nf >> 1][(nf & 1) * 2];
                    const uint32_t* bl = &bfl[nf >> 1][(nf & 1) * 2];
                    mma16816(acc[mf][nf], afh[mf], bh);
                    mma16816(acc[mf][nf], afh[mf], bl);
                    mma16816(acc[mf][nf], afl[mf], bh);
                }
        }
        __syncthreads();
    }

#pragma unroll
    for (int mf = 0; mf < 2; mf++)
#pragma unroll
        for (int nf = 0; nf < 4; nf++) {
            const int r  = m0 + wm * 32 + mf * 16 + (lane >> 2);
            const int cc = n0 + wn * 32 + nf * 8 + (lane & 3) * 2;
            *(float2*)(Cy + (size_t)r * Wv + cc) =
                make_float2(acc[mf][nf][0], acc[mf][nf][1]);
            *(float2*)(Cy + (size_t)(r + 8) * Wv + cc) =
                make_float2(acc[mf][nf][2], acc[mf][nf][3]);
        }
}

// ============================================================================
// Channel-mixing conv (1x3, pad 1 along w) + bias + rotary for q/k.
// ALL outputs stored [bc][f][w] (coalesced along w).
// ============================================================================
__global__ __launch_bounds__(256)
void conv_rot(const float* __restrict__ wq, const float* __restrict__ bq,
              const float* __restrict__ wk, const float* __restrict__ bk,
              const float* __restrict__ wv, const float* __restrict__ bv)
{
    int t = blockIdx.x * blockDim.x + threadIdx.x;
    const int w = t & (Wv - 1);
    int r = t >> 10;
    const int fp = r & (Fv / 2 - 1);
    r >>= 8;
    const int b = r & 1;
    const int p = r >> 1;
    if (p > 2) return;

    const float* wc   = (p == 0) ? wq : (p == 1) ? wk : wv;
    const float* bias = (p == 0) ? bq : (p == 1) ? bk : bv;
    const float* lin  = g_lin + (size_t)p * BCFWv + (size_t)b * Cv * FWv;
    const int f0 = fp * 2;

    float xin[4][2][3];
#pragma unroll
    for (int i = 0; i < 4; i++)
#pragma unroll
        for (int rr = 0; rr < 2; rr++) {
            const float* base = lin + (size_t)(i * Fv + f0 + rr) * Wv + w;
            xin[i][rr][0] = (w > 0)      ? base[-1] : 0.f;
            xin[i][rr][1] = base[0];
            xin[i][rr][2] = (w < Wv - 1) ? base[1]  : 0.f;
        }

    float cw = 1.f, sw = 0.f;
    if (p < 2) {
        const int pi = fp & 31;
        const float inv = exp2f(-(float)(2 * pi) * (13.287712379549449f / 64.0f));
        sincosf((float)w * inv, &sw, &cw);
    }

#pragma unroll
    for (int o = 0; o < 4; o++) {
        float y0 = bias[o], y1 = bias[o];
#pragma unroll
        for (int i = 0; i < 4; i++)
#pragma unroll
            for (int kk = 0; kk < 3; kk++) {
                const float wt = wc[(o * 4 + i) * 3 + kk];
                y0 += xin[i][0][kk] * wt;
                y1 += xin[i][1][kk] * wt;
            }
        const size_t idx = ((size_t)(b * Cv + o) * Fv + f0) * Wv + w;
        if (p < 2) {
            const float o0 = y0 * cw - y1 * sw;
            const float o1 = y1 * cw + y0 * sw;
            bf16* dst = (p == 0) ? g_qb : g_kb;
            dst[idx]      = __float2bfloat16(o0);
            dst[idx + Wv] = __float2bfloat16(o1);
        } else {
            bf16 h0, l0, h1, l1;
            split_bf16(y0, h0, l0);
            split_bf16(y1, h1, l1);
            g_vb_hi[idx] = h0; g_vb_lo[idx] = l0;
            g_vb_hi[idx + Wv] = h1; g_vb_lo[idx + Wv] = l1;
        }
    }
}

// ============================================================================
// FUSED attention, cp.async double-buffered K/V AND prev (prefetched to smem
// one stage ahead). P=exp(S) in registers; row sums in registers.
// Dynamic smem: Qs 17408 + K/V 3*18432... see offsets below (146432 B total).
// grid (8, 64), 256 threads.
// ============================================================================
#define AT_QS    0
#define AT_KS    17408
#define AT_VHS   (AT_KS  + 2 * 64 * 72 * 2)   // 35840
#define AT_VLS   (AT_VHS + 2 * 64 * 72 * 2)   // 54272
#define AT_PREV  (AT_VLS + 2 * 64 * 72 * 2)   // 72704
#define ATTN_SMEM (AT_PREV + 2 * 128 * 72 * 4) // 146432

__global__ __launch_bounds__(256)
void attn_fused(const float* __restrict__ prev, const float* __restrict__ mask,
                float* __restrict__ qk_out)
{
    extern __shared__ char sma[];
    bf16*  Qs  = (bf16*)(sma + AT_QS);     // [64][136]
    bf16*  Ks  = (bf16*)(sma + AT_KS);     // [2][64][72]
    bf16*  Vhs = (bf16*)(sma + AT_VHS);    // [2][64][72]
    bf16*  Vls = (bf16*)(sma + AT_VLS);    // [2][64][72]
    float* Pvs = (float*)(sma + AT_PREV);  // [2][128][72]

    const int tid = threadIdx.x, lane = tid & 31, wid = tid >> 5;
    const int bch = blockIdx.y;
    const int bc = bch >> 3, h = bch & 7;
    const int q0 = blockIdx.x * 128;

    const bf16* Qp = g_qb + ((size_t)bc * Fv + h * DHv) * Wv;
    const bf16* Kp = g_kb + ((size_t)bc * Fv + h * DHv) * Wv;
    const bf16* Vh = g_vb_hi + ((size_t)bc * Fv + h * DHv) * Wv;
    const bf16* Vl = g_vb_lo + ((size_t)bc * Fv + h * DHv) * Wv;
    const size_t sbase = (size_t)bch * Wv * Wv;

    const uint32_t ks_b  = smem_u32(Ks);
    const uint32_t vhs_b = smem_u32(Vhs);
    const uint32_t vls_b = smem_u32(Vls);
    const uint32_t pvs_b = smem_u32(Pvs);

    auto load_stage = [&](int st) {
        const int b = st & 1;
        const int kt = st * 64;
        // K, Vhi, Vlo: 64x64 bf16 each; 2 cp16 per thread per array
#pragma unroll
        for (int t = 0; t < 2; t++) {
            const int idx = tid + t * 256;
            const int row = idx >> 3, dc = (idx & 7) * 8;
            const uint32_t so = (b * 4608 + row * 72 + dc) * 2;
            const size_t go = (size_t)row * Wv + kt + dc;
            cp16(ks_b + so,  Kp + go);
            cp16(vhs_b + so, Vh + go);
            cp16(vls_b + so, Vl + go);
        }
        // prev: 128 x 64 fp32; 8 cp16 per thread
#pragma unroll
        for (int t = 0; t < 8; t++) {
            const int idx = tid + t * 256;
            const int row = idx >> 4, c4 = (idx & 15) * 4;
            cp16(pvs_b + (b * 9216 + row * 72 + c4) * 4,
                 prev + sbase + (size_t)(q0 + row) * Wv + kt + c4);
        }
        CP_COMMIT();
    };

    // load Q tile: rows d 0..63, cols q0..q0+127 (coalesced uint4)
#pragma unroll
    for (int t = 0; t < 4; t++) {
        const int idx = tid + t * 256;
        const int row = idx >> 4, c8 = (idx & 15) * 8;
        *(uint4*)&Qs[row * 136 + c8] = *(const uint4*)(Qp + (size_t)row * Wv + q0 + c8);
    }
    load_stage(0);
    __syncthreads();

    // Q A-fragments via ldsm.trans from [d][q]; chunk-invariant
    uint32_t qf[4][4];
    {
        const int qcol = wid * 16 + ((lane >> 3) & 1) * 8;
        const int krow = (lane & 7) + (lane >> 4) * 8;
#pragma unroll
        for (int ks = 0; ks < 4; ks++)
            ldsm4t(qf[ks], smem_u32(&Qs[(ks * 16 + krow) * 136 + qcol]));
    }

    float accO[8][4];
#pragma unroll
    for (int i = 0; i < 8; i++)
#pragma unroll
        for (int q = 0; q < 4; q++) accO[i][q] = 0.f;
    float rs0 = 0.f, rs1 = 0.f;

    const int r0 = lane >> 2;
    const int c0 = (lane & 3) * 2;
    const int qloc = wid * 16 + r0;          // local q row 0..127
    const int qrow = q0 + qloc;
    const float scale = 0.044194173824159216f;   // 1/sqrt(512)
    const int kbrow = (lane & 7) + ((lane >> 3) & 1) * 8;
    const int kbcol = ((lane >> 4) & 1) * 8;
    const int vbrow = (lane & 7) + ((lane >> 4) & 1) * 8;
    const int vbcol = ((lane >> 3) & 1) * 8;

    for (int st = 0; st < 16; st++) {
        const int b = st & 1;
        const int kt = st * 64;
        if (st + 1 < 16) { load_stage(st + 1); CP_WAIT(1); }
        else             { CP_WAIT(0); }
        __syncthreads();

        // ---- S = Q K^T (m16 x n64 per warp) ----
        float accS[8][4];
#pragma unroll
        for (int i = 0; i < 8; i++)
#pragma unroll
            for (int q = 0; q < 4; q++) accS[i][q] = 0.f;
#pragma unroll
        for (int ks = 0; ks < 4; ks++) {
            uint32_t kf[4][4];
#pragma unroll
            for (int np = 0; np < 4; np++)
                ldsm4t(kf[np], smem_u32(&Ks[b * 4608 + (ks * 16 + kbrow) * 72 + np * 16 + kbcol]));
#pragma unroll
            for (int np = 0; np < 4; np++) {
                mma16816(accS[2 * np],     qf[ks], &kf[np][0]);
                mma16816(accS[2 * np + 1], qf[ks], &kf[np][2]);
            }
        }

        // ---- epilogue: +prev(smem)+mask, write qk, exp -> P fragments ----
        uint32_t Phi[4][4], Plo[4][4];
        const float* pv_row0 = Pvs + b * 9216 + qloc * 72;
        const float* pv_row1 = pv_row0 + 8 * 72;
#pragma unroll
        for (int j = 0; j < 8; j++) {
            const int jc = j * 8 + c0;
            const int kk = kt + jc;
            const size_t off0 = sbase + (size_t)qrow * Wv + kk;
            const float2 pv0 = *(const float2*)(pv_row0 + jc);
            const float2 pv1 = *(const float2*)(pv_row1 + jc);
            const float2 mv0 = *(const float2*)(mask + (size_t)qrow * Wv + kk);
            const float2 mv1 = *(const float2*)(mask + (size_t)(qrow + 8) * Wv + kk);
            const float s00 = accS[j][0] * scale + pv0.x + mv0.x;
            const float s01 = accS[j][1] * scale + pv0.y + mv0.y;
            const float s10 = accS[j][2] * scale + pv1.x + mv1.x;
            const float s11 = accS[j][3] * scale + pv1.y + mv1.y;
            *(float2*)(qk_out + off0)          = make_float2(s00, s01);
            *(float2*)(qk_out + off0 + 8 * Wv) = make_float2(s10, s11);
            const float p00 = __expf(s00), p01 = __expf(s01);
            const float p10 = __expf(s10), p11 = __expf(s11);
            rs0 += p00 + p01;
            rs1 += p10 + p11;
            pack2(p00, p01, Phi[j >> 1][(j & 1) * 2],     Plo[j >> 1][(j & 1) * 2]);
            pack2(p10, p11, Phi[j >> 1][(j & 1) * 2 + 1], Plo[j >> 1][(j & 1) * 2 + 1]);
        }

        // ---- O += P V^T (3 products) ----
#pragma unroll
        for (int kp = 0; kp < 4; kp++) {
            uint32_t vh[4][4], vl[4][4];
#pragma unroll
            for (int dp = 0; dp < 4; dp++) {
                const uint32_t so = (b * 4608 + (dp * 16 + vbrow) * 72 + kp * 16 + vbcol) * 2;
                ldsm4(vh[dp], vhs_b + so);
                ldsm4(vl[dp], vls_b + so);
            }
#pragma unroll
            for (int dp = 0; dp < 4; dp++) {
                mma16816(accO[2 * dp],     Phi[kp], &vh[dp][0]);
                mma16816(accO[2 * dp + 1], Phi[kp], &vh[dp][2]);
                mma16816(accO[2 * dp],     Phi[kp], &vl[dp][0]);
                mma16816(accO[2 * dp + 1], Phi[kp], &vl[dp][2]);
                mma16816(accO[2 * dp],     Plo[kp], &vh[dp][0]);
                mma16816(accO[2 * dp + 1], Plo[kp], &vh[dp][2]);
            }
        }
        __syncthreads();
    }

    // row sums: reduce over the 4 lanes sharing each row
    rs0 += __shfl_xor_sync(0xffffffff, rs0, 1);
    rs0 += __shfl_xor_sync(0xffffffff, rs0, 2);
    rs1 += __shfl_xor_sync(0xffffffff, rs1, 1);
    rs1 += __shfl_xor_sync(0xffffffff, rs1, 2);
    const float inv0 = 1.f / rs0, inv1 = 1.f / rs1;

    // write O normalized -> g_at hi/lo [bc][w=q][f=h*64+d]
    bf16* hi = g_at_hi + (size_t)bc * FWv;
    bf16* lo = g_at_lo + (size_t)bc * FWv;
    const size_t row0 = (size_t)qrow * Fv + h * DHv;
#pragma unroll
    for (int j = 0; j < 8; j++) {
        const int d = j * 8 + c0;
        uint32_t ph, pl;
        pack2(accO[j][0] * inv0, accO[j][1] * inv0, ph, pl);
        *(uint32_t*)(hi + row0 + d) = ph;
        *(uint32_t*)(lo + row0 + d) = pl;
        pack2(accO[j][2] * inv1, accO[j][3] * inv1, ph, pl);
        *(uint32_t*)(hi + row0 + 8 * Fv + d) = ph;
        *(uint32_t*)(lo + row0 + 8 * Fv + d) = pl;
    }
}

// ============================================================================
// launch
// ============================================================================
extern "C" void kernel_launch(void* const* d_in, const int* in_sizes, int n_in,
                              void* d_out, int out_size)
{
    (void)in_sizes; (void)n_in; (void)out_size;
    const float* x       = (const float*)d_in[0];
    const float* prev    = (const float*)d_in[1];
    const float* mask    = (const float*)d_in[2];
    const float* wq_lin  = (const float*)d_in[3];
    const float* wq_conv = (const float*)d_in[4];
    const float* bq      = (const float*)d_in[5];
    const float* wk_lin  = (const float*)d_in[6];
    const float* wk_conv = (const float*)d_in[7];
    const float* bk      = (const float*)d_in[8];
    const float* wv_lin  = (const float*)d_in[9];
    const float* wv_conv = (const float*)d_in[10];
    const float* bv      = (const float*)d_in[11];
    const float* wo_lin  = (const float*)d_in[12];

    float* out = (float*)d_out;            // [2,4,512,1024]
    float* qk  = out + BCFWv;              // [2,4,8,1024,1024]

    float* glin = nullptr;
    bf16 *whi = nullptr, *wlo = nullptr, *xhi = nullptr, *xlo = nullptr;
    bf16 *ahi = nullptr, *alo = nullptr;
    cudaGetSymbolAddress((void**)&glin, g_lin);
    cudaGetSymbolAddress((void**)&whi, g_whi);
    cudaGetSymbolAddress((void**)&wlo, g_wlo);
    cudaGetSymbolAddress((void**)&xhi, g_xt_hi);
    cudaGetSymbolAddress((void**)&xlo, g_xt_lo);
    cudaGetSymbolAddress((void**)&ahi, g_at_hi);
    cudaGetSymbolAddress((void**)&alo, g_at_lo);

    cudaFuncSetAttribute(mc_gemm_mma, cudaFuncAttributeMaxDynamicSharedMemorySize, GEMM_SMEM);
    cudaFuncSetAttribute(attn_fused, cudaFuncAttributeMaxDynamicSharedMemorySize, ATTN_SMEM);

    const size_t WSZ = (size_t)Cv * Fv * Fv;   // 1M per weight set

    // 0) conversions
    cvt_weights<<<(4 * 1048576) / 256, 256>>>(wq_lin, wk_lin, wv_lin, wo_lin);
    transpose_x<<<dim3(Wv / 32, Fv / 32, BCv), 256>>>(x);

    // 1) q/k/v projections in ONE launch (z = set*8 + bc)
    mc_gemm_mma<<<dim3(Wv / 128, Fv / 128, 3 * BCv), 512, GEMM_SMEM>>>(whi, wlo, xhi, xlo, glin);

    // 2) conv + bias + rotary -> bf16 q,k,v (all [bc][f][w])
    const int conv_threads = 3 * Bv * (Fv / 2) * Wv;
    conv_rot<<<conv_threads / 256, 256>>>(wq_conv, bq, wk_conv, bk, wv_conv, bv);

    // 3+4) fused scores + softmax + P@V (cp.async pipelined)
    attn_fused<<<dim3(Wv / 128, BCv * Hv), 256, ATTN_SMEM>>>(prev, mask, qk);

    // 5) output projection
    mc_gemm_mma<<<dim3(Wv / 128, Fv / 128, BCv), 512, GEMM_SMEM>>>(whi + 3 * WSZ, wlo + 3 * WSZ,
                                                                   ahi, alo, out);
}

// round 15
// speedup vs baseline: 1.1700x; 1.1700x over previous
#include <cuda_runtime.h>
#include <cuda_bf16.h>
#include <math.h>
#include <cstdint>

#define Bv 2
#define Cv 4
#define Fv 512
#define Hv 8
#define Wv 1024
#define DHv 64
#define BCv (Bv*Cv)                 // 8
#define FWv (Fv*Wv)                 // 524288
#define BCFWv ((size_t)BCv*FWv)     // 4194304

typedef __nv_bfloat16 bf16;

// ---------------- scratch (device globals; no allocations allowed) ----------
__device__ __align__(256) float g_lin[3*BCFWv];        // post mc_linear q/k/v (fp32)
__device__ __align__(256) bf16 g_whi[4*(size_t)Cv*Fv*Fv];
__device__ __align__(256) bf16 g_wlo[4*(size_t)Cv*Fv*Fv];
__device__ __align__(256) bf16 g_xt_hi[BCFWv];         // x^T [bc][w][f]
__device__ __align__(256) bf16 g_xt_lo[BCFWv];
__device__ __align__(256) bf16 g_qb[BCFWv];            // q [bc][f][w]  (f = h*64+d)
__device__ __align__(256) bf16 g_kb[BCFWv];            // k [bc][f][w]
__device__ __align__(256) bf16 g_vb_hi[BCFWv];         // v [bc][f][w]
__device__ __align__(256) bf16 g_vb_lo[BCFWv];
__device__ __align__(256) bf16 g_at_hi[BCFWv];         // attn out [bc][w][f]
__device__ __align__(256) bf16 g_at_lo[BCFWv];

// ============================================================================
// mma.sync / ldmatrix helpers
// ============================================================================
__device__ __forceinline__ uint32_t smem_u32(const void* p) {
    uint32_t a;
    asm("{ .reg .u64 t; cvta.to.shared.u64 t, %1; cvt.u32.u64 %0, t; }" : "=r"(a) : "l"(p));
    return a;
}
__device__ __forceinline__ void ldsm4(uint32_t* r, uint32_t addr) {
    asm volatile("ldmatrix.sync.aligned.m8n8.x4.shared.b16 {%0,%1,%2,%3}, [%4];"
        : "=r"(r[0]), "=r"(r[1]), "=r"(r[2]), "=r"(r[3]) : "r"(addr));
}
__device__ __forceinline__ void ldsm4t(uint32_t* r, uint32_t addr) {
    asm volatile("ldmatrix.sync.aligned.m8n8.x4.trans.shared.b16 {%0,%1,%2,%3}, [%4];"
        : "=r"(r[0]), "=r"(r[1]), "=r"(r[2]), "=r"(r[3]) : "r"(addr));
}
__device__ __forceinline__ void mma16816(float* c, const uint32_t* a, const uint32_t* b) {
    asm volatile("mma.sync.aligned.m16n8k16.row.col.f32.bf16.bf16.f32 "
        "{%0,%1,%2,%3}, {%4,%5,%6,%7}, {%8,%9}, {%0,%1,%2,%3};"
        : "+f"(c[0]), "+f"(c[1]), "+f"(c[2]), "+f"(c[3])
        : "r"(a[0]), "r"(a[1]), "r"(a[2]), "r"(a[3]), "r"(b[0]), "r"(b[1]));
}
__device__ __forceinline__ void split_bf16(float v, bf16& h, bf16& l) {
    h = __float2bfloat16(v);
    l = __float2bfloat16(v - __bfloat162float(h));
}
__device__ __forceinline__ void pack2(float a, float b, uint32_t& hi, uint32_t& lo) {
    bf16 ha, la, hb, lb;
    split_bf16(a, ha, la);
    split_bf16(b, hb, lb);
    __nv_bfloat162 th{ha, hb}, tl{la, lb};
    hi = *(uint32_t*)&th;
    lo = *(uint32_t*)&tl;
}

// ============================================================================
// Conversion kernels
// ============================================================================
__global__ __launch_bounds__(256)
void cvt_weights(const float* __restrict__ w0, const float* __restrict__ w1,
                 const float* __restrict__ w2, const float* __restrict__ w3)
{
    size_t t = (size_t)blockIdx.x * 256 + threadIdx.x;   // 4 * 1M
    int m = (int)(t >> 20);
    const float* src = (m == 0) ? w0 : (m == 1) ? w1 : (m == 2) ? w2 : w3;
    float v = src[t & 1048575];
    bf16 h, l;
    split_bf16(v, h, l);
    g_whi[t] = h;
    g_wlo[t] = l;
}

__global__ __launch_bounds__(256)
void transpose_x(const float* __restrict__ x)
{
    __shared__ float tile[32][33];
    const int bc = blockIdx.z;
    const int w0 = blockIdx.x * 32, f0 = blockIdx.y * 32;
    const int tx = threadIdx.x & 31, ty = threadIdx.x >> 5;   // 32 x 8
    const float* src = x + (size_t)bc * FWv;
#pragma unroll
    for (int r = 0; r < 32; r += 8)
        tile[ty + r][tx] = src[(size_t)(f0 + ty + r) * Wv + w0 + tx];
    __syncthreads();
    bf16* hi = g_xt_hi + (size_t)bc * FWv;
    bf16* lo = g_xt_lo + (size_t)bc * FWv;
#pragma unroll
    for (int r = 0; r < 32; r += 8) {
        float v = tile[tx][ty + r];
        size_t idx = (size_t)(w0 + ty + r) * Fv + f0 + tx;
        bf16 h, l;
        split_bf16(v, h, l);
        hi[idx] = h;
        lo[idx] = l;
    }
}

// ============================================================================
// Per-channel GEMM via mma.sync.
// NPROD=3: split hi/lo, 3 products (v / out projections — precision-critical).
// NPROD=1: single bf16 product (q/k projections — they get rounded to bf16
//          downstream anyway; skips lo-tile loads/stores and 2/3 of MMAs).
// 512 threads, 4x4 warp grid, warp tile 32x32. grid z = nsets*8.
// ============================================================================
template <int NPROD>
__global__ __launch_bounds__(512)
void mc_gemm_mma(const bf16* __restrict__ Whi, const bf16* __restrict__ Wlo,
                 const bf16* __restrict__ Xhi, const bf16* __restrict__ Xlo,
                 float* __restrict__ Y)
{
    __shared__ __align__(16) bf16 As[2][128][40];   // [hi/lo][m][k]
    __shared__ __align__(16) bf16 Bs[2][128][40];   // [hi/lo][n][k]

    const int tid = threadIdx.x, lane = tid & 31, wid = tid >> 5;
    const int wm = wid >> 2, wn = wid & 3;          // 4 x 4 warps
    const int s = blockIdx.z >> 3, bc = blockIdx.z & 7, c = bc & 3;
    const int m0 = blockIdx.y * 128, n0 = blockIdx.x * 128;

    const bf16* Ah = Whi + ((size_t)s * Cv + c) * Fv * Fv;
    const bf16* Al = Wlo + ((size_t)s * Cv + c) * Fv * Fv;
    const bf16* Bh = Xhi + (size_t)bc * FWv;
    const bf16* Bl = Xlo + (size_t)bc * FWv;
    float* Cy = Y + ((size_t)s * BCv + bc) * FWv;

    const int g_row = tid >> 2;            // 0..127
    const int g_kc  = (tid & 3) * 8;

    uint4 ra[2], rb[2];
    auto loadg = [&](int k0) {
        ra[0] = *(const uint4*)(Ah + (size_t)(m0 + g_row) * Fv + k0 + g_kc);
        rb[0] = *(const uint4*)(Bh + (size_t)(n0 + g_row) * Fv + k0 + g_kc);
        if (NPROD == 3) {
            ra[1] = *(const uint4*)(Al + (size_t)(m0 + g_row) * Fv + k0 + g_kc);
            rb[1] = *(const uint4*)(Bl + (size_t)(n0 + g_row) * Fv + k0 + g_kc);
        }
    };

    float acc[2][4][4];
#pragma unroll
    for (int i = 0; i < 2; i++)
#pragma unroll
        for (int j = 0; j < 4; j++)
#pragma unroll
            for (int q = 0; q < 4; q++) acc[i][j][q] = 0.f;

    loadg(0);
    const int NIT = Fv / 32;               // 16
    for (int it = 0; it < NIT; it++) {
        *(uint4*)&As[0][g_row][g_kc] = ra[0];
        *(uint4*)&Bs[0][g_row][g_kc] = rb[0];
        if (NPROD == 3) {
            *(uint4*)&As[1][g_row][g_kc] = ra[1];
            *(uint4*)&Bs[1][g_row][g_kc] = rb[1];
        }
        __syncthreads();
        if (it < NIT - 1) loadg((it + 1) * 32);

#pragma unroll
        for (int ks = 0; ks < 2; ks++) {
            uint32_t afh[2][4], afl[2][4], bfh[2][4], bfl[2][4];
            const int acol = ks * 16 + (lane >> 4) * 8;
            const int arow_l = lane & 15;
#pragma unroll
            for (int mf = 0; mf < 2; mf++) {
                const int r = wm * 32 + mf * 16 + arow_l;
                ldsm4(afh[mf], smem_u32(&As[0][r][acol]));
                if (NPROD == 3) ldsm4(afl[mf], smem_u32(&As[1][r][acol]));
            }
            const int brow_l = (lane & 7) + ((lane >> 4) & 1) * 8;
            const int bcol = ks * 16 + ((lane >> 3) & 1) * 8;
#pragma unroll
            for (int nh = 0; nh < 2; nh++) {
                const int r = wn * 32 + nh * 16 + brow_l;
                ldsm4(bfh[nh], smem_u32(&Bs[0][r][bcol]));
                if (NPROD == 3) ldsm4(bfl[nh], smem_u32(&Bs[1][r][bcol]));
            }
#pragma unroll
            for (int mf = 0; mf < 2; mf++)
#pragma unroll
                for (int nf = 0; nf < 4; nf++) {
                    const uint32_t* bh = &bfh[nf >> 1][(nf & 1) * 2];
                    mma16816(acc[mf][nf], afh[mf], bh);
                    if (NPROD == 3) {
                        const uint32_t* bl = &bfl[nf >> 1][(nf & 1) * 2];
                        mma16816(acc[mf][nf], afh[mf], bl);
                        mma16816(acc[mf][nf], afl[mf], bh);
                    }
                }
        }
        __syncthreads();
    }

#pragma unroll
    for (int mf = 0; mf < 2; mf++)
#pragma unroll
        for (int nf = 0; nf < 4; nf++) {
            const int r  = m0 + wm * 32 + mf * 16 + (lane >> 2);
            const int cc = n0 + wn * 32 + nf * 8 + (lane & 3) * 2;
            *(float2*)(Cy + (size_t)r * Wv + cc) =
                make_float2(acc[mf][nf][0], acc[mf][nf][1]);
            *(float2*)(Cy + (size_t)(r + 8) * Wv + cc) =
                make_float2(acc[mf][nf][2], acc[mf][nf][3]);
        }
}

// ============================================================================
// Channel-mixing conv (1x3, pad 1 along w) + bias + rotary for q/k.
// ALL outputs stored [bc][f][w] (coalesced along w).
// ============================================================================
__global__ __launch_bounds__(256)
void conv_rot(const float* __restrict__ wq, const float* __restrict__ bq,
              const float* __restrict__ wk, const float* __restrict__ bk,
              const float* __restrict__ wv, const float* __restrict__ bv)
{
    int t = blockIdx.x * blockDim.x + threadIdx.x;
    const int w = t & (Wv - 1);
    int r = t >> 10;
    const int fp = r & (Fv / 2 - 1);
    r >>= 8;
    const int b = r & 1;
    const int p = r >> 1;
    if (p > 2) return;

    const float* wc   = (p == 0) ? wq : (p == 1) ? wk : wv;
    const float* bias = (p == 0) ? bq : (p == 1) ? bk : bv;
    const float* lin  = g_lin + (size_t)p * BCFWv + (size_t)b * Cv * FWv;
    const int f0 = fp * 2;

    float xin[4][2][3];
#pragma unroll
    for (int i = 0; i < 4; i++)
#pragma unroll
        for (int rr = 0; rr < 2; rr++) {
            const float* base = lin + (size_t)(i * Fv + f0 + rr) * Wv + w;
            xin[i][rr][0] = (w > 0)      ? base[-1] : 0.f;
            xin[i][rr][1] = base[0];
            xin[i][rr][2] = (w < Wv - 1) ? base[1]  : 0.f;
        }

    float cw = 1.f, sw = 0.f;
    if (p < 2) {
        const int pi = fp & 31;
        const float inv = exp2f(-(float)(2 * pi) * (13.287712379549449f / 64.0f));
        sincosf((float)w * inv, &sw, &cw);
    }

#pragma unroll
    for (int o = 0; o < 4; o++) {
        float y0 = bias[o], y1 = bias[o];
#pragma unroll
        for (int i = 0; i < 4; i++)
#pragma unroll
            for (int kk = 0; kk < 3; kk++) {
                const float wt = wc[(o * 4 + i) * 3 + kk];
                y0 += xin[i][0][kk] * wt;
                y1 += xin[i][1][kk] * wt;
            }
        const size_t idx = ((size_t)(b * Cv + o) * Fv + f0) * Wv + w;
        if (p < 2) {
            const float o0 = y0 * cw - y1 * sw;
            const float o1 = y1 * cw + y0 * sw;
            bf16* dst = (p == 0) ? g_qb : g_kb;
            dst[idx]      = __float2bfloat16(o0);
            dst[idx + Wv] = __float2bfloat16(o1);
        } else {
            bf16 h0, l0, h1, l1;
            split_bf16(y0, h0, l0);
            split_bf16(y1, h1, l1);
            g_vb_hi[idx] = h0; g_vb_lo[idx] = l0;
            g_vb_hi[idx + Wv] = h1; g_vb_lo[idx + Wv] = l1;
        }
    }
}

// ============================================================================
// FUSED attention (R10 form — best known). Q,K,V stored [bc][f][w]; smem tiles
// [d][w]; Q/K fragments via ldmatrix.trans. P=exp(S) and row sums in registers.
// grid (8, 64), 256 threads.
// ============================================================================
__global__ __launch_bounds__(256)
void attn_fused(const float* __restrict__ prev, const float* __restrict__ mask,
                float* __restrict__ qk_out)
{
    __shared__ __align__(16) bf16 Qs[64][136];   // [d][q 128]
    __shared__ __align__(16) bf16 Ks[64][72];    // [d][k 64]
    __shared__ __align__(16) bf16 Vhs[64][72];   // [d][k 64]
    __shared__ __align__(16) bf16 Vls[64][72];

    const int tid = threadIdx.x, lane = tid & 31, wid = tid >> 5;
    const int bch = blockIdx.y;
    const int bc = bch >> 3, h = bch & 7;
    const int q0 = blockIdx.x * 128;

    const bf16* Qp = g_qb + ((size_t)bc * Fv + h * DHv) * Wv;
    const bf16* Kp = g_kb + ((size_t)bc * Fv + h * DHv) * Wv;
    const bf16* Vh = g_vb_hi + ((size_t)bc * Fv + h * DHv) * Wv;
    const bf16* Vl = g_vb_lo + ((size_t)bc * Fv + h * DHv) * Wv;
    const size_t sbase = (size_t)bch * Wv * Wv;

    // load Q tile: rows d 0..63, cols q0..q0+127 (coalesced uint4)
#pragma unroll
    for (int t = 0; t < 4; t++) {
        const int idx = tid + t * 256;
        const int row = idx >> 4, c8 = (idx & 15) * 8;
        *(uint4*)&Qs[row][c8] = *(const uint4*)(Qp + (size_t)row * Wv + q0 + c8);
    }
    __syncthreads();

    // Q A-fragments via ldsm.trans from [d][q]; chunk-invariant
    uint32_t qf[4][4];
    {
        const int qcol = wid * 16 + ((lane >> 3) & 1) * 8;
        const int krow = (lane & 7) + (lane >> 4) * 8;
#pragma unroll
        for (int ks = 0; ks < 4; ks++)
            ldsm4t(qf[ks], smem_u32(&Qs[ks * 16 + krow][qcol]));
    }

    float accO[8][4];
#pragma unroll
    for (int i = 0; i < 8; i++)
#pragma unroll
        for (int q = 0; q < 4; q++) accO[i][q] = 0.f;
    float rs0 = 0.f, rs1 = 0.f;

    const int r0 = lane >> 2;
    const int c0 = (lane & 3) * 2;
    const int qrow = q0 + wid * 16 + r0;
    const float scale = 0.044194173824159216f;   // 1/sqrt(512)
    const int kbrow = (lane & 7) + ((lane >> 3) & 1) * 8;
    const int kbcol = ((lane >> 4) & 1) * 8;
    const int vbrow = (lane & 7) + ((lane >> 4) & 1) * 8;
    const int vbcol = ((lane >> 3) & 1) * 8;

    for (int kt = 0; kt < Wv; kt += 64) {
        __syncthreads();
#pragma unroll
        for (int t = 0; t < 2; t++) {
            const int idx = tid + t * 256;
            const int row = idx >> 3, dc = (idx & 7) * 8;
            *(uint4*)&Ks[row][dc]  = *(const uint4*)(Kp + (size_t)row * Wv + kt + dc);
            *(uint4*)&Vhs[row][dc] = *(const uint4*)(Vh + (size_t)row * Wv + kt + dc);
            *(uint4*)&Vls[row][dc] = *(const uint4*)(Vl + (size_t)row * Wv + kt + dc);
        }
        __syncthreads();

        // ---- S = Q K^T (m16 x n64 per warp) ----
        float accS[8][4];
#pragma unroll
        for (int i = 0; i < 8; i++)
#pragma unroll
            for (int q = 0; q < 4; q++) accS[i][q] = 0.f;
#pragma unroll
        for (int ks = 0; ks < 4; ks++) {
            uint32_t kf[4][4];
#pragma unroll
            for (int np = 0; np < 4; np++)
                ldsm4t(kf[np], smem_u32(&Ks[ks * 16 + kbrow][np * 16 + kbcol]));
#pragma unroll
            for (int np = 0; np < 4; np++) {
                mma16816(accS[2 * np],     qf[ks], &kf[np][0]);
                mma16816(accS[2 * np + 1], qf[ks], &kf[np][2]);
            }
        }

        // ---- epilogue: +prev+mask, write qk, exp -> P fragments ----
        uint32_t Phi[4][4], Plo[4][4];
#pragma unroll
        for (int j = 0; j < 8; j++) {
            const int kk = kt + j * 8 + c0;
            const size_t off0 = sbase + (size_t)qrow * Wv + kk;
            const float2 pv0 = *(const float2*)(prev + off0);
            const float2 pv1 = *(const float2*)(prev + off0 + 8 * Wv);
            const float2 mv0 = *(const float2*)(mask + (size_t)qrow * Wv + kk);
            const float2 mv1 = *(const float2*)(mask + (size_t)(qrow + 8) * Wv + kk);
            const float s00 = accS[j][0] * scale + pv0.x + mv0.x;
            const float s01 = accS[j][1] * scale + pv0.y + mv0.y;
            const float s10 = accS[j][2] * scale + pv1.x + mv1.x;
            const float s11 = accS[j][3] * scale + pv1.y + mv1.y;
            *(float2*)(qk_out + off0)          = make_float2(s00, s01);
            *(float2*)(qk_out + off0 + 8 * Wv) = make_float2(s10, s11);
            const float p00 = __expf(s00), p01 = __expf(s01);
            const float p10 = __expf(s10), p11 = __expf(s11);
            rs0 += p00 + p01;
            rs1 += p10 + p11;
            pack2(p00, p01, Phi[j >> 1][(j & 1) * 2],     Plo[j >> 1][(j & 1) * 2]);
            pack2(p10, p11, Phi[j >> 1][(j & 1) * 2 + 1], Plo[j >> 1][(j & 1) * 2 + 1]);
        }

        // ---- O += P V^T (3 products) ----
#pragma unroll
        for (int kp = 0; kp < 4; kp++) {
            uint32_t vh[4][4], vl[4][4];
#pragma unroll
            for (int dp = 0; dp < 4; dp++) {
                ldsm4(vh[dp], smem_u32(&Vhs[dp * 16 + vbrow][kp * 16 + vbcol]));
                ldsm4(vl[dp], smem_u32(&Vls[dp * 16 + vbrow][kp * 16 + vbcol]));
            }
#pragma unroll
            for (int dp = 0; dp < 4; dp++) {
                mma16816(accO[2 * dp],     Phi[kp], &vh[dp][0]);
                mma16816(accO[2 * dp + 1], Phi[kp], &vh[dp][2]);
                mma16816(accO[2 * dp],     Phi[kp], &vl[dp][0]);
                mma16816(accO[2 * dp + 1], Phi[kp], &vl[dp][2]);
                mma16816(accO[2 * dp],     Plo[kp], &vh[dp][0]);
                mma16816(accO[2 * dp + 1], Plo[kp], &vh[dp][2]);
            }
        }
    }

    // row sums: reduce over the 4 lanes sharing each row
    rs0 += __shfl_xor_sync(0xffffffff, rs0, 1);
    rs0 += __shfl_xor_sync(0xffffffff, rs0, 2);
    rs1 += __shfl_xor_sync(0xffffffff, rs1, 1);
    rs1 += __shfl_xor_sync(0xffffffff, rs1, 2);
    const float inv0 = 1.f / rs0, inv1 = 1.f / rs1;

    // write O normalized -> g_at hi/lo [bc][w=q][f=h*64+d]
    bf16* hi = g_at_hi + (size_t)bc * FWv;
    bf16* lo = g_at_lo + (size_t)bc * FWv;
    const size_t row0 = (size_t)qrow * Fv + h * DHv;
#pragma unroll
    for (int j = 0; j < 8; j++) {
        const int d = j * 8 + c0;
        uint32_t ph, pl;
        pack2(accO[j][0] * inv0, accO[j][1] * inv0, ph, pl);
        *(uint32_t*)(hi + row0 + d) = ph;
        *(uint32_t*)(lo + row0 + d) = pl;
        pack2(accO[j][2] * inv1, accO[j][3] * inv1, ph, pl);
        *(uint32_t*)(hi + row0 + 8 * Fv + d) = ph;
        *(uint32_t*)(lo + row0 + 8 * Fv + d) = pl;
    }
}

// ============================================================================
// launch
// ============================================================================
extern "C" void kernel_launch(void* const* d_in, const int* in_sizes, int n_in,
                              void* d_out, int out_size)
{
    (void)in_sizes; (void)n_in; (void)out_size;
    const float* x       = (const float*)d_in[0];
    const float* prev    = (const float*)d_in[1];
    const float* mask    = (const float*)d_in[2];
    const float* wq_lin  = (const float*)d_in[3];
    const float* wq_conv = (const float*)d_in[4];
    const float* bq      = (const float*)d_in[5];
    const float* wk_lin  = (const float*)d_in[6];
    const float* wk_conv = (const float*)d_in[7];
    const float* bk      = (const float*)d_in[8];
    const float* wv_lin  = (const float*)d_in[9];
    const float* wv_conv = (const float*)d_in[10];
    const float* bv      = (const float*)d_in[11];
    const float* wo_lin  = (const float*)d_in[12];

    float* out = (float*)d_out;            // [2,4,512,1024]
    float* qk  = out + BCFWv;              // [2,4,8,1024,1024]

    float* glin = nullptr;
    bf16 *whi = nullptr, *wlo = nullptr, *xhi = nullptr, *xlo = nullptr;
    bf16 *ahi = nullptr, *alo = nullptr;
    cudaGetSymbolAddress((void**)&glin, g_lin);
    cudaGetSymbolAddress((void**)&whi, g_whi);
    cudaGetSymbolAddress((void**)&wlo, g_wlo);
    cudaGetSymbolAddress((void**)&xhi, g_xt_hi);
    cudaGetSymbolAddress((void**)&xlo, g_xt_lo);
    cudaGetSymbolAddress((void**)&ahi, g_at_hi);
    cudaGetSymbolAddress((void**)&alo, g_at_lo);

    const size_t WSZ = (size_t)Cv * Fv * Fv;   // 1M per weight set

    // 0) conversions
    cvt_weights<<<(4 * 1048576) / 256, 256>>>(wq_lin, wk_lin, wv_lin, wo_lin);
    transpose_x<<<dim3(Wv / 32, Fv / 32, BCv), 256>>>(x);

    // 1a) q + k projections: single-product (their outputs get rounded to
    //     bf16 before QK^T anyway; error stays at the already-present 2^-9 level)
    mc_gemm_mma<1><<<dim3(Wv / 128, Fv / 128, 2 * BCv), 512>>>(whi, wlo, xhi, xlo, glin);
    // 1b) v projection: full 3-product precision (flows linearly into `out`)
    mc_gemm_mma<3><<<dim3(Wv / 128, Fv / 128, BCv), 512>>>(whi + 2 * WSZ, wlo + 2 * WSZ,
                                                           xhi, xlo, glin + 2 * BCFWv);

    // 2) conv + bias + rotary -> bf16 q,k,v (all [bc][f][w])
    const int conv_threads = 3 * Bv * (Fv / 2) * Wv;
    conv_rot<<<conv_threads / 256, 256>>>(wq_conv, bq, wk_conv, bk, wv_conv, bv);

    // 3+4) fused scores + softmax + P@V
    attn_fused<<<dim3(Wv / 128, BCv * Hv), 256>>>(prev, mask, qk);

    // 5) output projection: full 3-product precision
    mc_gemm_mma<3><<<dim3(Wv / 128, Fv / 128, BCv), 512>>>(whi + 3 * WSZ, wlo + 3 * WSZ,
                                                           ahi, alo, out);
}